// round 16
// baseline (speedup 1.0000x reference)
#include <cuda_runtime.h>
#include <cuda_fp16.h>
#include <mma.h>

using namespace nvcuda;

// Problem constants (shapes fixed by the reference).
#define NMAX   100000
#define NEMAX  1600000
#define FEAT   64
#define SCAN_T 256

// ---------------- device scratch (no allocations allowed) ----------------
// g_t16 padded by 128 rows: last GEMM block stores a full 128-row tile unguarded.
__device__ __half   g_t16[(NMAX + 128) * FEAT];  // fp16 transformed features (gather input)
__device__ __half   g_h16[NMAX * FEAT];          // fp16 hidden activations (iso-prescaled)
__device__ unsigned g_degout[NMAX];
__device__ unsigned g_degin[NMAX];
__device__ float    g_iso[NMAX];          // D_out^{-1/2}
__device__ float    g_isi[NMAX];          // D_in^{-1/2}
__device__ int      g_rowstart[NMAX + 1]; // CSR row offsets (by dst)
__device__ int      g_cursor[NMAX];       // fill cursors
__device__ int      g_csr[NEMAX];         // src ids grouped by dst
__device__ int      g_blksum[512];        // scan block totals

// ---------------- degree / normalizer kernels ----------------

__global__ void zero_deg_kernel(int nn) {
    int i = blockIdx.x * blockDim.x + threadIdx.x;
    if (i < nn) { g_degout[i] = 0u; g_degin[i] = 0u; g_cursor[i] = 0; }
    if (i == 0) g_rowstart[0] = 0;
}

__global__ void deg_kernel(const int* __restrict__ src, const int* __restrict__ dst, int ne) {
    int e = blockIdx.x * blockDim.x + threadIdx.x;
    if (e < ne) {
        atomicAdd(&g_degout[src[e]], 1u);
        atomicAdd(&g_degin[dst[e]], 1u);
    }
}

__global__ void inv_kernel(int nn) {
    int i = blockIdx.x * blockDim.x + threadIdx.x;
    if (i < nn) {
        g_iso[i] = rsqrtf(fmaxf((float)g_degout[i], 1.0f));
        g_isi[i] = rsqrtf(fmaxf((float)g_degin[i], 1.0f));
    }
}

// ---------------- prefix-sum (exclusive) over in-degrees -> g_rowstart ----------------
__global__ void scanA_kernel(int nn) {
    __shared__ int sh[SCAN_T];
    int tid = threadIdx.x;
    int i = blockIdx.x * SCAN_T + tid;
    int v = (i < nn) ? (int)g_degin[i] : 0;
    sh[tid] = v;
    __syncthreads();
#pragma unroll
    for (int off = 1; off < SCAN_T; off <<= 1) {
        int t = (tid >= off) ? sh[tid - off] : 0;
        __syncthreads();
        sh[tid] += t;
        __syncthreads();
    }
    if (i < nn) g_rowstart[i + 1] = sh[tid];
    if (tid == SCAN_T - 1) g_blksum[blockIdx.x] = sh[tid];
}

__global__ void scanB_kernel(int nb) {
    __shared__ int sh[512];
    int tid = threadIdx.x;
    sh[tid] = (tid < nb) ? g_blksum[tid] : 0;
    __syncthreads();
#pragma unroll
    for (int off = 1; off < 512; off <<= 1) {
        int t = (tid >= off) ? sh[tid - off] : 0;
        __syncthreads();
        sh[tid] += t;
        __syncthreads();
    }
    g_blksum[tid] = sh[tid];
}

__global__ void scanC_kernel(int nn) {
    int i = blockIdx.x * SCAN_T + threadIdx.x;
    if (i < nn && blockIdx.x > 0) g_rowstart[i + 1] += g_blksum[blockIdx.x - 1];
}

__global__ void csr_fill_kernel(const int* __restrict__ src, const int* __restrict__ dst, int ne) {
    int e = blockIdx.x * blockDim.x + threadIdx.x;
    if (e < ne) {
        int d = dst[e];
        int pos = atomicAdd(&g_cursor[d], 1);
        g_csr[g_rowstart[d] + pos] = src[e];
    }
}

// ---------------- dense transform via fp16 HMMA tensor cores ----------------
// T = X @ W (X already iso-prescaled unless EPI_SCALE, which scales rows in epilogue).
// Whole W and whole 128xK X tile resident in dynamic smem; all loads issued up
// front (high MLP), ONE sync, then all MMAs. Epilogue St overlaps the smem.
template <int K, bool IN16, bool EPI_SCALE>
__global__ __launch_bounds__(256, 4)
void gemm_mma_kernel(const void* __restrict__ Xv, const float* __restrict__ W, int nn) {
    constexpr int WLD = FEAT + 8;     // 72 halves
    constexpr int XLD = K + 8;        // 136 (K=128) / 72 (K=64) halves
    constexpr int SLD = FEAT + 4;     // 68 floats

    extern __shared__ __align__(16) char smem[];
    __half (*Ws)[WLD] = reinterpret_cast<__half (*)[WLD]>(smem);                  // K x WLD
    __half (*Xs)[XLD] = reinterpret_cast<__half (*)[XLD]>(smem + K * WLD * 2);    // 128 x XLD
    float  (*St)[SLD] = reinterpret_cast<float  (*)[SLD]>(smem);                  // overlaps all

    const int tid = threadIdx.x;
    const int wid = tid >> 5;
    const int warp_row = wid >> 1;    // 0..3 -> 32-row band
    const int warp_col = wid & 1;     // 0..1 -> 32-col band
    const int nodeBase = blockIdx.x * 128;

    // Load whole W (K x 64 fp32 -> fp16 smem).
#pragma unroll
    for (int i = tid; i < K * (FEAT / 4); i += 256) {
        int r = i >> 4, c4 = (i & 15) * 4;
        float4 v = __ldg(reinterpret_cast<const float4*>(&W[r * FEAT + c4]));
        __half2 h0 = __floats2half2_rn(v.x, v.y);
        __half2 h1 = __floats2half2_rn(v.z, v.w);
        uint2 pack;
        pack.x = *reinterpret_cast<unsigned*>(&h0);
        pack.y = *reinterpret_cast<unsigned*>(&h1);
        *reinterpret_cast<uint2*>(&Ws[r][c4]) = pack;
    }
    // Load whole X tile (128 x K), no scaling here.
#pragma unroll
    for (int i = tid; i < 128 * (K / 8); i += 256) {
        int r = i / (K / 8), c8 = (i % (K / 8)) * 8;
        int node = nodeBase + r;
        uint4 pack = make_uint4(0u, 0u, 0u, 0u);
        if (node < nn) {
            if (IN16) {
                pack = __ldg(reinterpret_cast<const uint4*>(
                    reinterpret_cast<const __half*>(Xv) + (size_t)node * K + c8));
            } else {
                const float* row = reinterpret_cast<const float*>(Xv) + (size_t)node * K + c8;
                float4 v0 = __ldg(reinterpret_cast<const float4*>(row));
                float4 v1 = __ldg(reinterpret_cast<const float4*>(row + 4));
                __half2 h0 = __floats2half2_rn(v0.x, v0.y);
                __half2 h1 = __floats2half2_rn(v0.z, v0.w);
                __half2 h2 = __floats2half2_rn(v1.x, v1.y);
                __half2 h3 = __floats2half2_rn(v1.z, v1.w);
                pack.x = *reinterpret_cast<unsigned*>(&h0);
                pack.y = *reinterpret_cast<unsigned*>(&h1);
                pack.z = *reinterpret_cast<unsigned*>(&h2);
                pack.w = *reinterpret_cast<unsigned*>(&h3);
            }
        }
        *reinterpret_cast<uint4*>(&Xs[r][c8]) = pack;
    }
    __syncthreads();

    wmma::fragment<wmma::accumulator, 16, 16, 16, float> acc[2][2];
#pragma unroll
    for (int r = 0; r < 2; r++)
#pragma unroll
        for (int c = 0; c < 2; c++) wmma::fill_fragment(acc[r][c], 0.0f);

#pragma unroll
    for (int kk = 0; kk < K; kk += 16) {
        wmma::fragment<wmma::matrix_a, 16, 16, 16, __half, wmma::row_major> a[2];
        wmma::fragment<wmma::matrix_b, 16, 16, 16, __half, wmma::row_major> b[2];
#pragma unroll
        for (int r = 0; r < 2; r++)
            wmma::load_matrix_sync(a[r], &Xs[warp_row * 32 + r * 16][kk], XLD);
#pragma unroll
        for (int c = 0; c < 2; c++)
            wmma::load_matrix_sync(b[c], &Ws[kk][warp_col * 32 + c * 16], WLD);
#pragma unroll
        for (int r = 0; r < 2; r++)
#pragma unroll
            for (int c = 0; c < 2; c++)
                wmma::mma_sync(acc[r][c], a[r], b[c], acc[r][c]);
    }
    __syncthreads();   // all mma smem reads done before St overwrites

    // Epilogue: fp32 tile -> smem stage -> (optional iso row-scale) -> fp16 stores.
#pragma unroll
    for (int r = 0; r < 2; r++)
#pragma unroll
        for (int c = 0; c < 2; c++)
            wmma::store_matrix_sync(&St[warp_row * 32 + r * 16][warp_col * 32 + c * 16],
                                    acc[r][c], SLD, wmma::mem_row_major);
    __syncthreads();

#pragma unroll
    for (int i = tid; i < 128 * (FEAT / 8); i += 256) {
        int r = i >> 3;
        int c8 = (i & 7) * 8;
        int node = nodeBase + r;
        float s = 1.0f;
        if (EPI_SCALE) s = (node < nn) ? g_iso[node] : 0.0f;
        float4 f0 = *reinterpret_cast<float4*>(&St[r][c8]);
        float4 f1 = *reinterpret_cast<float4*>(&St[r][c8 + 4]);
        __half2 h0 = __floats2half2_rn(f0.x * s, f0.y * s);
        __half2 h1 = __floats2half2_rn(f0.z * s, f0.w * s);
        __half2 h2 = __floats2half2_rn(f1.x * s, f1.y * s);
        __half2 h3 = __floats2half2_rn(f1.z * s, f1.w * s);
        uint4 pack;
        pack.x = *reinterpret_cast<unsigned*>(&h0);
        pack.y = *reinterpret_cast<unsigned*>(&h1);
        pack.z = *reinterpret_cast<unsigned*>(&h2);
        pack.w = *reinterpret_cast<unsigned*>(&h3);
        *reinterpret_cast<uint4*>(&g_t16[(size_t)node * FEAT + c8]) = pack;
    }
}

// ---------------- CSR gather + finalize ----------------
// 16 lanes per node; each lane owns 4 half columns (8 B per edge), unroll 8.
// OUT16: store iso-prescaled fp16 hidden (feeds pure GEMM); else fp32 final out.
template <int RELU, bool OUT16>
__global__ void gather_kernel(const float* __restrict__ b, void* __restrict__ outv, int nn) {
    int idx = blockIdx.x * blockDim.x + threadIdx.x;
    int node = idx >> 4;
    int c = (idx & 15) << 2;          // half-column base (0,4,...,60)
    if (node >= nn) return;

    int rs = g_rowstart[node];
    int re = g_rowstart[node + 1];

    float acc0 = 0.f, acc1 = 0.f, acc2 = 0.f, acc3 = 0.f;

#pragma unroll 8
    for (int p = rs; p < re; ++p) {
        int s = __ldg(&g_csr[p]);     // same addr across 16 lanes -> broadcast wavefront
        uint2 u = __ldg(reinterpret_cast<const uint2*>(&g_t16[(size_t)s * FEAT + c]));
        float2 f0 = __half22float2(*reinterpret_cast<__half2*>(&u.x));
        float2 f1 = __half22float2(*reinterpret_cast<__half2*>(&u.y));
        acc0 += f0.x; acc1 += f0.y; acc2 += f1.x; acc3 += f1.y;
    }

    float sN = g_isi[node];
    float4 bb = *reinterpret_cast<const float4*>(&b[c]);
    float o0 = acc0 * sN + bb.x;
    float o1 = acc1 * sN + bb.y;
    float o2 = acc2 * sN + bb.z;
    float o3 = acc3 * sN + bb.w;
    if (RELU) {
        o0 = fmaxf(o0, 0.f); o1 = fmaxf(o1, 0.f);
        o2 = fmaxf(o2, 0.f); o3 = fmaxf(o3, 0.f);
    }
    if (OUT16) {
        float sO = g_iso[node];       // prescale for next layer's pure GEMM
        __half2 h0 = __floats2half2_rn(o0 * sO, o1 * sO);
        __half2 h1 = __floats2half2_rn(o2 * sO, o3 * sO);
        uint2 pack;
        pack.x = *reinterpret_cast<unsigned*>(&h0);
        pack.y = *reinterpret_cast<unsigned*>(&h1);
        *reinterpret_cast<uint2*>(reinterpret_cast<__half*>(outv) + (size_t)node * FEAT + c) = pack;
    } else {
        *reinterpret_cast<float4*>(reinterpret_cast<float*>(outv) + (size_t)node * FEAT + c) =
            make_float4(o0, o1, o2, o3);
    }
}

// ---------------- launch ----------------
extern "C" void kernel_launch(void* const* d_in, const int* in_sizes, int n_in,
                              void* d_out, int out_size) {
    const float* x   = (const float*)d_in[0];
    const int*   src = (const int*)d_in[1];
    const int*   dst = (const int*)d_in[2];
    const float* W1  = (const float*)d_in[3];
    const float* b1  = (const float*)d_in[4];
    const float* W2  = (const float*)d_in[5];
    const float* b2  = (const float*)d_in[6];
    const float* W3  = (const float*)d_in[7];
    const float* b3  = (const float*)d_in[8];

    const int nn = in_sizes[0] / 128;   // 100000
    const int ne = in_sizes[1];         // 1600000

    // Dynamic smem sizes: max(W + X tile, fp32 stage 34816).
    const int SMEM_G128 = 128 * 72 * 2 + 128 * 136 * 2;   // 53248
    const int SMEM_G64  = 34816;                           // stage dominates

    // One-time setup (first call is the uncaptured correctness run).
    static __half* h16_ptr = nullptr;
    static cudaStream_t s_side = nullptr;
    static cudaEvent_t ev_fork = nullptr, ev_join = nullptr;
    if (h16_ptr == nullptr) {
        cudaGetSymbolAddress((void**)&h16_ptr, g_h16);
        cudaStreamCreateWithFlags(&s_side, cudaStreamNonBlocking);
        cudaEventCreateWithFlags(&ev_fork, cudaEventDisableTiming);
        cudaEventCreateWithFlags(&ev_join, cudaEventDisableTiming);
        cudaFuncSetAttribute(gemm_mma_kernel<128, false, true>,
                             cudaFuncAttributeMaxDynamicSharedMemorySize, SMEM_G128);
        cudaFuncSetAttribute(gemm_mma_kernel<64, true, false>,
                             cudaFuncAttributeMaxDynamicSharedMemorySize, SMEM_G64);
    }

    const int T = 256;
    const int nodeBlk = (nn + T - 1) / T;
    const int edgeBlk = (ne + T - 1) / T;
    const int gathBlk = (nn * 16 + T - 1) / T;
    const int gemmBlk = (nn + 127) / 128;
    const int scanNB  = (nn + SCAN_T - 1) / SCAN_T;

    // ---- shared prerequisites: degrees + normalizers (main stream) ----
    zero_deg_kernel<<<nodeBlk, T>>>(nn);
    deg_kernel<<<edgeBlk, T>>>(src, dst, ne);
    inv_kernel<<<nodeBlk, T>>>(nn);

    // ---- fork: gemm1 (needs iso only) runs concurrently with CSR build ----
    cudaEventRecord(ev_fork, 0);
    cudaStreamWaitEvent(s_side, ev_fork, 0);
    gemm_mma_kernel<128, false, true><<<gemmBlk, 256, SMEM_G128, s_side>>>(x, W1, nn);
    cudaEventRecord(ev_join, s_side);

    scanA_kernel<<<scanNB, SCAN_T>>>(nn);
    scanB_kernel<<<1, 512>>>(scanNB);
    scanC_kernel<<<scanNB, SCAN_T>>>(nn);
    csr_fill_kernel<<<edgeBlk, T>>>(src, dst, ne);

    // ---- join: gather1 needs both CSR (main) and t16 (side) ----
    cudaStreamWaitEvent(0, ev_join, 0);
    gather_kernel<1, true><<<gathBlk, T>>>(b1, h16_ptr, nn);

    // ---- layer 2: h16(64, prescaled) -> h16(64, prescaled), relu ----
    gemm_mma_kernel<64, true, false><<<gemmBlk, 256, SMEM_G64>>>(h16_ptr, W2, nn);
    gather_kernel<1, true><<<gathBlk, T>>>(b2, h16_ptr, nn);

    // ---- layer 3: h16(64, prescaled) -> out(64, fp32), no relu ----
    gemm_mma_kernel<64, true, false><<<gemmBlk, 256, SMEM_G64>>>(h16_ptr, W3, nn);
    gather_kernel<0, false><<<gathBlk, T>>>(b3, d_out, nn);
}